// round 1
// baseline (speedup 1.0000x reference)
#include <cuda_runtime.h>
#include <math_constants.h>

#define PI_F 3.14159265358979323846f

// Per-box intermediate results (N <= 8192 guard; actual N = 1024)
__device__ float g_box_mean[8192];
__device__ int   g_box_valid[8192];

__global__ void __launch_bounds__(256)
box_kernel(const float* __restrict__ wl,
           const float* __restrict__ Ry,
           const float2* __restrict__ points,
           const float* __restrict__ density,
           const float* __restrict__ center,
           int P) {
    const int n = blockIdx.x;

    // ---- per-box constants (computed redundantly by every thread; cheap) ----
    const float w  = wl[2 * n];
    const float l  = wl[2 * n + 1];
    const float ry = Ry[n];
    const float c0 = center[2 * n];
    const float c1 = center[2 * n + 1];

    const float init_theta = atanf(w / l);
    const float length     = sqrtf(w * w + l * l) * 0.5f;

    float angs[4];
    angs[0] = init_theta + ry;
    angs[1] = PI_F - init_theta + ry;
    angs[2] = PI_F + init_theta + ry;
    angs[3] = -init_theta + ry;

    float cx[4], cy[4];
#pragma unroll
    for (int j = 0; j < 4; j++) {
        cx[j] = length * cosf(angs[j]) + c0;
        cy[j] = length * sinf(angs[j]) + c1;
    }

    float ry2 = ry;
    if (ry2 == PI_F * 0.5f) ry2 -= 0.0001f;
    if (ry2 == 0.0f)        ry2 += 0.0001f;
    const float k1 = tanf(ry2);
    const float k2 = tanf(ry2 + PI_F * 0.5f);

    const float b11 = cy[0] - k1 * cx[0];
    const float b12 = cy[2] - k1 * cx[2];
    const float b21 = cy[0] - k2 * cx[0];
    const float b22 = cy[2] - k2 * cx[2];

    float ks[4] = {k1, k2, k1, k2};
    float bs[4] = {b11, b22, b12, b21};

    // rounded corner coords + edge bounding intervals (edge j: corner j -> corner nxt[j])
    float cxr[4], cyr[4];
#pragma unroll
    for (int j = 0; j < 4; j++) {
        cxr[j] = rintf(cx[j] * 10000.0f);
        cyr[j] = rintf(cy[j] * 10000.0f);
    }
    const int nxt[4] = {1, 2, 3, 0};
    float lox[4], hix[4], loy[4], hiy[4];
#pragma unroll
    for (int j = 0; j < 4; j++) {
        const int jn = nxt[j];
        lox[j] = fminf(cxr[j], cxr[jn]);
        hix[j] = fmaxf(cxr[j], cxr[jn]);
        loy[j] = fminf(cyr[j], cyr[jn]);
        hiy[j] = fmaxf(cyr[j], cyr[jn]);
    }

    // ---- per-point loop ----
    const float2* pts  = points  + (size_t)n * P;
    const float*  dens = density + (size_t)n * P;

    float lsum = 0.0f;
    int   lcnt = 0;

    for (int p = threadIdx.x; p < P; p += blockDim.x) {
        const float2 pt = pts[p];
        const float px = (pt.x == 0.0f) ? 0.0001f : pt.x;
        const float py = pt.y;
        const float slope = py / px;

        float best_cen = CUDART_INF_F;
        float best_dis = 0.0f;
        int   m = 0;

#pragma unroll
        for (int j = 0; j < 4; j++) {
            const float denom = slope - ks[j];
            const float ix  = bs[j] / denom;                 // matches jnp: bs/denom
            const float iy  = (bs[j] * slope) / denom;       // matches jnp: bs*slope/denom
            const float dis = fabsf(ix - px) + fabsf(iy - py);
            if (j == 0) best_dis = dis;                      // argmin default index 0
            const float cen = sqrtf(ix * ix + iy * iy);
            const float irx = rintf(ix * 10000.0f);
            const float iry = rintf(iy * 10000.0f);
            const bool mask = ((irx > lox[j]) & (irx < hix[j])) |
                              ((iry > loy[j]) & (iry < hiy[j]));
            if (mask) {
                m++;
                if (cen < best_cen) {                        // strict <: first-min tie-break
                    best_cen = cen;
                    best_dis = dis;
                }
            }
        }

        if (m == 2) {
            lsum += best_dis / dens[p];
            lcnt += 1;
        }
    }

    // ---- block reduction ----
    __shared__ float ssum[256];
    __shared__ int   scnt[256];
    const int t = threadIdx.x;
    ssum[t] = lsum;
    scnt[t] = lcnt;
    __syncthreads();
#pragma unroll
    for (int off = 128; off > 0; off >>= 1) {
        if (t < off) {
            ssum[t] += ssum[t + off];
            scnt[t] += scnt[t + off];
        }
        __syncthreads();
    }

    if (t == 0) {
        const int   cnt = scnt[0];
        g_box_valid[n] = (cnt >= 3) ? 1 : 0;
        g_box_mean[n]  = ssum[0] / (float)max(cnt, 1);
    }
}

__global__ void __launch_bounds__(256)
finalize_kernel(float* __restrict__ out, int N) {
    __shared__ float ssum[256];
    __shared__ int   scnt[256];
    const int t = threadIdx.x;
    float s = 0.0f;
    int   c = 0;
    for (int i = t; i < N; i += blockDim.x) {
        if (g_box_valid[i]) {
            s += g_box_mean[i];
            c += 1;
        }
    }
    ssum[t] = s;
    scnt[t] = c;
    __syncthreads();
#pragma unroll
    for (int off = 128; off > 0; off >>= 1) {
        if (t < off) {
            ssum[t] += ssum[t + off];
            scnt[t] += scnt[t + off];
        }
        __syncthreads();
    }
    if (t == 0) {
        out[0] = ssum[0] / (float)max(scnt[0], 1);
    }
}

extern "C" void kernel_launch(void* const* d_in, const int* in_sizes, int n_in,
                              void* d_out, int out_size) {
    const float* wl      = (const float*)d_in[0];
    const float* Ry      = (const float*)d_in[1];
    const float2* points = (const float2*)d_in[2];
    const float* density = (const float*)d_in[3];
    const float* center  = (const float*)d_in[4];
    float* out = (float*)d_out;

    const int N = in_sizes[1];                 // Ry has N elements
    const int P = in_sizes[3] / N;             // density has N*P elements

    box_kernel<<<N, 256>>>(wl, Ry, points, density, center, P);
    finalize_kernel<<<1, 256>>>(out, N);
}

// round 2
// speedup vs baseline: 1.7025x; 1.7025x over previous
#include <cuda_runtime.h>
#include <math_constants.h>

#define PI_F 3.14159265358979323846f

// Per-box intermediate results (N <= 8192 guard; actual N = 1024)
__device__ float        g_box_mean[8192];
__device__ int          g_box_valid[8192];
__device__ unsigned int g_done = 0;   // last-block ticket; reset each call by last block

__device__ __forceinline__ float frcp_approx(float x) {
    float r;
    asm("rcp.approx.f32 %0, %1;" : "=f"(r) : "f"(x));
    return r;
}

__global__ void __launch_bounds__(256)
box_kernel(const float* __restrict__ wl,
           const float* __restrict__ Ry,
           const float4* __restrict__ points4,   // 2 points per float4
           const float* __restrict__ density,
           const float* __restrict__ center,
           float* __restrict__ out,
           int P) {
    const int n = blockIdx.x;
    const int t = threadIdx.x;

    // shared setup: [0]=k1 [1]=k2 [2..5]=bs [6..9]=lox [10..13]=hix [14..17]=loy [18..21]=hiy
    __shared__ float s_set[22];
    __shared__ int   s_last;

    if (t == 0) {
        const float w  = wl[2 * n];
        const float l  = wl[2 * n + 1];
        const float ry = Ry[n];
        const float c0 = center[2 * n];
        const float c1 = center[2 * n + 1];

        const float init_theta = atanf(w / l);
        const float length     = sqrtf(w * w + l * l) * 0.5f;

        float angs[4];
        angs[0] = init_theta + ry;
        angs[1] = PI_F - init_theta + ry;
        angs[2] = PI_F + init_theta + ry;
        angs[3] = -init_theta + ry;

        float cx[4], cy[4];
#pragma unroll
        for (int j = 0; j < 4; j++) {
            cx[j] = length * cosf(angs[j]) + c0;
            cy[j] = length * sinf(angs[j]) + c1;
        }

        float ry2 = ry;
        if (ry2 == PI_F * 0.5f) ry2 -= 0.0001f;
        if (ry2 == 0.0f)        ry2 += 0.0001f;
        const float k1 = tanf(ry2);
        const float k2 = tanf(ry2 + PI_F * 0.5f);

        s_set[0] = k1;
        s_set[1] = k2;
        s_set[2] = cy[0] - k1 * cx[0];   // b11
        s_set[3] = cy[0] - k2 * cx[0];   // b22 position: bs = {b11, b22, b12, b21}
        // careful: bs order is {b11, b22, b12, b21}
        s_set[3] = cy[2] - k2 * cx[2];   // b22
        s_set[4] = cy[2] - k1 * cx[2];   // b12
        s_set[5] = cy[0] - k2 * cx[0];   // b21

        float cxr[4], cyr[4];
#pragma unroll
        for (int j = 0; j < 4; j++) {
            cxr[j] = rintf(cx[j] * 10000.0f);
            cyr[j] = rintf(cy[j] * 10000.0f);
        }
        const int nxt[4] = {1, 2, 3, 0};
#pragma unroll
        for (int j = 0; j < 4; j++) {
            const int jn = nxt[j];
            s_set[6  + j] = fminf(cxr[j], cxr[jn]);   // lox
            s_set[10 + j] = fmaxf(cxr[j], cxr[jn]);   // hix
            s_set[14 + j] = fminf(cyr[j], cyr[jn]);   // loy
            s_set[18 + j] = fmaxf(cyr[j], cyr[jn]);   // hiy
        }
    }
    __syncthreads();

    const float k1 = s_set[0];
    const float k2 = s_set[1];
    float bs[4], lox[4], hix[4], loy[4], hiy[4];
#pragma unroll
    for (int j = 0; j < 4; j++) {
        bs[j]  = s_set[2 + j];
        lox[j] = s_set[6 + j];
        hix[j] = s_set[10 + j];
        loy[j] = s_set[14 + j];
        hiy[j] = s_set[18 + j];
    }

    const float4* pts4 = points4 + (size_t)n * (P / 2);
    const float*  dens = density + (size_t)n * P;

    float lsum = 0.0f;
    int   lcnt = 0;

    const int half = P / 2;
    for (int i = t; i < half; i += 256) {
        const float4 q = pts4[i];

#pragma unroll
        for (int h = 0; h < 2; h++) {
            const float rawx = h ? q.z : q.x;
            const float py   = h ? q.w : q.y;
            const float px   = (rawx == 0.0f) ? 0.0001f : rawx;
            const float slope = py * frcp_approx(px);

            const float rA = frcp_approx(slope - k1);   // edges 0, 2
            const float rB = frcp_approx(slope - k2);   // edges 1, 3

            float best_cen2 = CUDART_INF_F;
            float best_dis  = 0.0f;
            int   m = 0;

#pragma unroll
            for (int j = 0; j < 4; j++) {
                const float r  = (j & 1) ? rB : rA;
                const float ix = bs[j] * r;
                const float iy = ix * slope;
                const float dis = fabsf(ix - px) + fabsf(iy - py);
                if (j == 0) best_dis = dis;             // argmin default index 0
                const float cen2 = fmaf(ix, ix, iy * iy);  // sqrt dropped: monotone
                const float irx = rintf(ix * 10000.0f);
                const float iry = rintf(iy * 10000.0f);
                const bool mask = ((irx > lox[j]) & (irx < hix[j])) |
                                  ((iry > loy[j]) & (iry < hiy[j]));
                if (mask) {
                    m++;
                    if (cen2 < best_cen2) {             // strict <: first-min tie-break
                        best_cen2 = cen2;
                        best_dis  = dis;
                    }
                }
            }

            if (m == 2) {
                lsum += best_dis * frcp_approx(dens[2 * i + h]);
                lcnt += 1;
            }
        }
    }

    // ---- block reduction ----
    __shared__ float ssum[256];
    __shared__ int   scnt[256];
    ssum[t] = lsum;
    scnt[t] = lcnt;
    __syncthreads();
#pragma unroll
    for (int off = 128; off > 0; off >>= 1) {
        if (t < off) {
            ssum[t] += ssum[t + off];
            scnt[t] += scnt[t + off];
        }
        __syncthreads();
    }

    if (t == 0) {
        const int cnt = scnt[0];
        g_box_valid[n] = (cnt >= 3) ? 1 : 0;
        g_box_mean[n]  = ssum[0] / (float)max(cnt, 1);
        __threadfence();
        const unsigned int ticket = atomicAdd(&g_done, 1u);
        s_last = (ticket == gridDim.x - 1) ? 1 : 0;
    }
    __syncthreads();

    // ---- fused finalize: only the last block to finish runs this ----
    if (s_last) {
        const int N = gridDim.x;
        float s = 0.0f;
        int   c = 0;
        for (int i = t; i < N; i += 256) {
            if (g_box_valid[i]) {
                s += g_box_mean[i];
                c += 1;
            }
        }
        ssum[t] = s;
        scnt[t] = c;
        __syncthreads();
#pragma unroll
        for (int off = 128; off > 0; off >>= 1) {
            if (t < off) {
                ssum[t] += ssum[t + off];
                scnt[t] += scnt[t + off];
            }
            __syncthreads();
        }
        if (t == 0) {
            out[0] = ssum[0] / (float)max(scnt[0], 1);
            g_done = 0;   // reset for next (graph-replayed) call
        }
    }
}

extern "C" void kernel_launch(void* const* d_in, const int* in_sizes, int n_in,
                              void* d_out, int out_size) {
    const float*  wl      = (const float*)d_in[0];
    const float*  Ry      = (const float*)d_in[1];
    const float4* points4 = (const float4*)d_in[2];
    const float*  density = (const float*)d_in[3];
    const float*  center  = (const float*)d_in[4];
    float* out = (float*)d_out;

    const int N = in_sizes[1];        // Ry has N elements
    const int P = in_sizes[3] / N;    // density has N*P elements

    box_kernel<<<N, 256>>>(wl, Ry, points4, density, center, out, P);
}

// round 3
// speedup vs baseline: 1.9808x; 1.1635x over previous
#include <cuda_runtime.h>
#include <math_constants.h>

#define PI_F 3.14159265358979323846f

// Per-box intermediate results (N <= 8192 guard; actual N = 1024)
__device__ float        g_box_mean[8192];
__device__ int          g_box_valid[8192];
__device__ unsigned int g_done = 0;   // last-block ticket; reset by last block each call

__device__ __forceinline__ float frcp_approx(float x) {
    float r;
    asm("rcp.approx.f32 %0, %1;" : "=f"(r) : "f"(x));
    return r;
}

__global__ void __launch_bounds__(128, 8)
box_kernel(const float* __restrict__ wl,
           const float* __restrict__ Ry,
           const float4* __restrict__ points4,   // 2 points per float4
           const float4* __restrict__ density4,  // 4 densities per float4
           const float* __restrict__ center,
           float* __restrict__ out,
           int P) {
    const int n = blockIdx.x;
    const int t = threadIdx.x;

    // setup: [0]=k1 [1]=k2 [2..5]=bs [6..9]=midx [10..13]=halfx [14..17]=midy [18..21]=halfy
    __shared__ float s_set[22];
    __shared__ int   s_last;

    if (t == 0) {
        const float w  = wl[2 * n];
        const float l  = wl[2 * n + 1];
        const float ry = Ry[n];
        const float c0 = center[2 * n];
        const float c1 = center[2 * n + 1];

        const float init_theta = atanf(w / l);
        const float length     = sqrtf(w * w + l * l) * 0.5f;

        float angs[4];
        angs[0] = init_theta + ry;
        angs[1] = PI_F - init_theta + ry;
        angs[2] = PI_F + init_theta + ry;
        angs[3] = -init_theta + ry;

        float cx[4], cy[4];
#pragma unroll
        for (int j = 0; j < 4; j++) {
            cx[j] = length * cosf(angs[j]) + c0;
            cy[j] = length * sinf(angs[j]) + c1;
        }

        float ry2 = ry;
        if (ry2 == PI_F * 0.5f) ry2 -= 0.0001f;
        if (ry2 == 0.0f)        ry2 += 0.0001f;
        const float k1 = tanf(ry2);
        const float k2 = tanf(ry2 + PI_F * 0.5f);

        s_set[0] = k1;
        s_set[1] = k2;
        // bs order = {b11, b22, b12, b21}
        s_set[2] = cy[0] - k1 * cx[0];   // b11
        s_set[3] = cy[2] - k2 * cx[2];   // b22
        s_set[4] = cy[2] - k1 * cx[2];   // b12
        s_set[5] = cy[0] - k2 * cx[0];   // b21

        float cxr[4], cyr[4];
#pragma unroll
        for (int j = 0; j < 4; j++) {
            cxr[j] = rintf(cx[j] * 10000.0f);
            cyr[j] = rintf(cy[j] * 10000.0f);
        }
        const int nxt[4] = {1, 2, 3, 0};
#pragma unroll
        for (int j = 0; j < 4; j++) {
            const int jn = nxt[j];
            const float lox = fminf(cxr[j], cxr[jn]);
            const float hix = fmaxf(cxr[j], cxr[jn]);
            const float loy = fminf(cyr[j], cyr[jn]);
            const float hiy = fmaxf(cyr[j], cyr[jn]);
            s_set[6  + j] = (lox + hix) * 0.5f;   // midx (exact: integer-valued bounds)
            s_set[10 + j] = (hix - lox) * 0.5f;   // halfx
            s_set[14 + j] = (loy + hiy) * 0.5f;   // midy
            s_set[18 + j] = (hiy - loy) * 0.5f;   // halfy
        }
    }
    __syncthreads();

    const float k1 = s_set[0];
    const float k2 = s_set[1];
    float bs[4], midx[4], halfx[4], midy[4], halfy[4];
#pragma unroll
    for (int j = 0; j < 4; j++) {
        bs[j]    = s_set[2 + j];
        midx[j]  = s_set[6 + j];
        halfx[j] = s_set[10 + j];
        midy[j]  = s_set[14 + j];
        halfy[j] = s_set[18 + j];
    }

    const float4* pts4 = points4  + (size_t)n * (P / 2);
    const float4* dns4 = density4 + (size_t)n * (P / 4);

    float lsum = 0.0f;
    int   lcnt = 0;

    const int quarter = P / 4;   // 4 points per iteration
    for (int i = t; i < quarter; i += 128) {
        const float4 q0 = pts4[2 * i];
        const float4 q1 = pts4[2 * i + 1];
        const float4 d4 = dns4[i];

        float PX[4] = {q0.x, q0.z, q1.x, q1.z};
        float PY[4] = {q0.y, q0.w, q1.y, q1.w};
        float DN[4] = {d4.x, d4.y, d4.z, d4.w};

#pragma unroll
        for (int h = 0; h < 4; h++) {
            const float px = (PX[h] == 0.0f) ? 0.0001f : PX[h];
            const float py = PY[h];
            const float slope = py * frcp_approx(px);

            const float rA = frcp_approx(slope - k1);   // edges 0, 2
            const float rB = frcp_approx(slope - k2);   // edges 1, 3

            float best_aix = CUDART_INF_F;   // argmin key: |ix| (monotone with cen)
            float best_dis = 0.0f;
            int   m = 0;

#pragma unroll
            for (int j = 0; j < 4; j++) {
                const float r  = (j & 1) ? rB : rA;
                const float ix = bs[j] * r;
                const float iy = ix * slope;
                const float dis = fabsf(ix - px) + fabsf(iy - py);
                const float irx = rintf(ix * 10000.0f);
                const float iry = rintf(iy * 10000.0f);
                const bool mask = (fabsf(irx - midx[j]) < halfx[j]) |
                                  (fabsf(iry - midy[j]) < halfy[j]);
                m += mask ? 1 : 0;
                const bool better = mask & (fabsf(ix) < best_aix);
                best_aix = better ? fabsf(ix) : best_aix;
                best_dis = better ? dis : best_dis;
            }

            if (m == 2) {
                lsum += best_dis * frcp_approx(DN[h]);
                lcnt += 1;
            }
        }
    }

    // ---- block reduction (128 threads) ----
    __shared__ float ssum[128];
    __shared__ int   scnt[128];
    ssum[t] = lsum;
    scnt[t] = lcnt;
    __syncthreads();
#pragma unroll
    for (int off = 64; off > 0; off >>= 1) {
        if (t < off) {
            ssum[t] += ssum[t + off];
            scnt[t] += scnt[t + off];
        }
        __syncthreads();
    }

    if (t == 0) {
        const int cnt = scnt[0];
        g_box_valid[n] = (cnt >= 3) ? 1 : 0;
        g_box_mean[n]  = ssum[0] / (float)max(cnt, 1);
        __threadfence();
        const unsigned int ticket = atomicAdd(&g_done, 1u);
        s_last = (ticket == gridDim.x - 1) ? 1 : 0;
    }
    __syncthreads();

    // ---- fused finalize: only the last block to finish runs this ----
    if (s_last) {
        const int N = gridDim.x;
        float s = 0.0f;
        int   c = 0;
        for (int i = t; i < N; i += 128) {
            if (g_box_valid[i]) {
                s += g_box_mean[i];
                c += 1;
            }
        }
        ssum[t] = s;
        scnt[t] = c;
        __syncthreads();
#pragma unroll
        for (int off = 64; off > 0; off >>= 1) {
            if (t < off) {
                ssum[t] += ssum[t + off];
                scnt[t] += scnt[t + off];
            }
            __syncthreads();
        }
        if (t == 0) {
            out[0] = ssum[0] / (float)max(scnt[0], 1);
            g_done = 0;   // reset for next graph replay
        }
    }
}

extern "C" void kernel_launch(void* const* d_in, const int* in_sizes, int n_in,
                              void* d_out, int out_size) {
    const float*  wl      = (const float*)d_in[0];
    const float*  Ry      = (const float*)d_in[1];
    const float4* points4 = (const float4*)d_in[2];
    const float4* dens4   = (const float4*)d_in[3];
    const float*  center  = (const float*)d_in[4];
    float* out = (float*)d_out;

    const int N = in_sizes[1];        // Ry has N elements
    const int P = in_sizes[3] / N;    // density has N*P elements

    box_kernel<<<N, 128>>>(wl, Ry, points4, dens4, center, out, P);
}